// round 1
// baseline (speedup 1.0000x reference)
#include <cuda_runtime.h>

#define Bn 4
#define Tn 512
#define Cn 8
#define Fn 257
#define BFn (Bn*Fn)            // 1028
#define Dn 40
#define TPn 505                // T - delay - taps + 1
#define NBTCF (Bn*Tn*Cn*Fn)    // 4210688

// Workspaces (no allocation allowed)
__device__ float2 g_Y[(size_t)BFn * Tn * Cn];   // (b,f,t,c) interleaved complex
__device__ float  g_w[(size_t)BFn * Tn];        // inverse power weights
__device__ float2 g_E[(size_t)BFn * Cn * Tn];   // enhanced, (b,f,c,t)

// ---------------------------------------------------------------------------
// Kernel 1: pack (B,T,C,F) re/im -> (b,f,t,c) float2, compute power + 1/power
// ---------------------------------------------------------------------------
__global__ __launch_bounds__(256) void k_prep(const float* __restrict__ re,
                                              const float* __restrict__ im,
                                              float* __restrict__ outP) {
    int b  = blockIdx.y;
    int t0 = blockIdx.x * 8;
    for (int f = threadIdx.x; f < Fn; f += 256) {
        #pragma unroll
        for (int tl = 0; tl < 8; tl++) {
            int t = t0 + tl;
            const float* pr = re + ((size_t)(b * Tn + t) * Cn) * Fn + f;
            const float* pi = im + ((size_t)(b * Tn + t) * Cn) * Fn + f;
            float rr[8], ii[8];
            float acc = 0.f;
            #pragma unroll
            for (int c = 0; c < 8; c++) {
                rr[c] = pr[c * Fn];
                ii[c] = pi[c * Fn];
                acc += rr[c] * rr[c] + ii[c] * ii[c];
            }
            float2* dst = g_Y + ((size_t)(b * Fn + f) * Tn + t) * Cn;
            #pragma unroll
            for (int c = 0; c < 8; c += 2) {
                float4 v = make_float4(rr[c], ii[c], rr[c + 1], ii[c + 1]);
                *(float4*)(dst + c) = v;
            }
            float p = fmaxf(acc * 0.125f, 1e-6f);
            int pidx = (b * Fn + f) * Tn + t;
            outP[pidx] = p;
            g_w[pidx] = 1.0f / p;
        }
    }
}

// ---------------------------------------------------------------------------
// Kernel 2: per-(b,f) WPE. 1028 blocks, 256 threads.
// ---------------------------------------------------------------------------
__global__ __launch_bounds__(256) void k_wpe() {
    const int bf  = blockIdx.x;
    const int tid = threadIdx.x;

    // shared layout (phases overlap on purpose):
    //  [0,32768)        sY  : Y t-major  [t*8+c]           (phase 1)
    //  [32768,34816)    sw  : inv power  [512]             (phase 1)
    //  [33088,48448)    sM  : 40x48 complex M / L / G      (phase >=1 end)
    //  [0,33088)        sYt : Y c-major  [c*517+t]         (phase 3)
    __shared__ __align__(16) char s_raw[48464];
    float2* sY   = (float2*)s_raw;
    float*  sw   = (float*)(s_raw + 32768);
    float2* sM   = (float2*)(s_raw + 33088);
    float2* sYt  = (float2*)s_raw;
    float*  sEps = (float*)(s_raw + 48448);

    const float2* Yg = g_Y + (size_t)bf * (Tn * Cn);
    for (int idx = tid; idx < Tn * Cn; idx += 256) sY[idx] = Yg[idx];
    for (int idx = tid; idx < Tn; idx += 256) sw[idx] = g_w[(size_t)bf * Tn + idx];
    __syncthreads();

    // ---------------- Phase 1: M = [R | P] accumulation (upper tiles only) --
    // tiles: it in [0,10) rows of 4, jt in [it,12) cols of 4 (cols 40..47 = P)
    int tile = tid % 75;
    int ph   = tid / 75;      // 0,1,2 active; 3 idle
    int it = 0, r2 = tile;
    while (r2 >= 12 - it) { r2 -= 12 - it; it++; }
    int jt = it + r2;

    int ki = it >> 1;
    int d0 = (it & 1) * 4;
    int aBase = (4 - ki) * 8 + d0;           // row offset added to t*8
    int bBase;
    if (jt >= 10) bBase = 7 * 8 + (jt - 10) * 4;   // P column: Y[:, t+7]
    else          bBase = (4 - (jt >> 1)) * 8 + (jt & 1) * 4;

    float accR[16], accI[16];
    #pragma unroll
    for (int q = 0; q < 16; q++) { accR[q] = 0.f; accI[q] = 0.f; }

    if (ph < 3) {
        for (int t = ph; t < TPn; t += 3) {
            float w = sw[t + 7];
            const float4* pa = (const float4*)(sY + t * 8 + aBase);
            float4 a0 = pa[0], a1 = pa[1];
            const float4* pb = (const float4*)(sY + t * 8 + bBase);
            float4 b0 = pb[0], b1 = pb[1];
            float ax[4] = {a0.x, a0.z, a1.x, a1.z};
            float ay[4] = {a0.y, a0.w, a1.y, a1.w};
            float bx[4] = {b0.x * w, b0.z * w, b1.x * w, b1.z * w};
            float by[4] = {b0.y * w, b0.w * w, b1.y * w, b1.w * w};
            #pragma unroll
            for (int r = 0; r < 4; r++) {
                #pragma unroll
                for (int s = 0; s < 4; s++) {
                    // conj(a) * (w*b)
                    accR[r * 4 + s] += ax[r] * bx[s] + ay[r] * by[s];
                    accI[r * 4 + s] += ax[r] * by[s] - ay[r] * bx[s];
                }
            }
        }
    }
    __syncthreads();   // everyone done reading sY/sw before sM region reused

    if (ph == 1) {
        #pragma unroll
        for (int r = 0; r < 4; r++)
            #pragma unroll
            for (int s = 0; s < 4; s++)
                sM[(it * 4 + r) * 48 + jt * 4 + s] =
                    make_float2(accR[r * 4 + s], accI[r * 4 + s]);
    }
    __syncthreads();
    if (ph == 2) {
        #pragma unroll
        for (int r = 0; r < 4; r++)
            #pragma unroll
            for (int s = 0; s < 4; s++) {
                int idx = (it * 4 + r) * 48 + jt * 4 + s;
                float2 v = sM[idx];
                v.x += accR[r * 4 + s]; v.y += accI[r * 4 + s];
                sM[idx] = v;
            }
    }
    __syncthreads();
    if (ph == 0) {
        #pragma unroll
        for (int r = 0; r < 4; r++)
            #pragma unroll
            for (int s = 0; s < 4; s++) {
                int i = it * 4 + r, j = jt * 4 + s;
                float2 v = sM[i * 48 + j];
                v.x += accR[r * 4 + s]; v.y += accI[r * 4 + s];
                sM[i * 48 + j] = v;
                if (jt < 10 && jt > it)                  // mirror into lower
                    sM[j * 48 + i] = make_float2(v.x, -v.y);
            }
    }
    __syncthreads();

    // ---------------- diag loading --------------------------------------
    if (tid == 0) {
        float tr = 0.f;
        for (int i = 0; i < Dn; i++) tr += sM[i * 48 + i].x;
        *sEps = 1e-10f * tr / (float)Dn;
    }
    __syncthreads();
    if (tid < Dn) sM[tid * 48 + tid].x += *sEps;
    __syncthreads();

    // ---------------- Cholesky (lower, in place) -------------------------
    for (int k = 0; k < Dn; k++) {
        if (tid == 0) sM[k * 48 + k].x = sqrtf(fmaxf(sM[k * 48 + k].x, 1e-30f));
        __syncthreads();
        float inv = 1.0f / sM[k * 48 + k].x;
        int i = k + 1 + tid;
        if (i < Dn) {
            float2 v = sM[i * 48 + k];
            v.x *= inv; v.y *= inv;
            sM[i * 48 + k] = v;
        }
        __syncthreads();
        int n = 39 - k;
        int npairs = n * (n + 1) / 2;
        for (int p = tid; p < npairs; p += 256) {
            int m = (int)((sqrtf(8.f * (float)p + 1.f) - 1.f) * 0.5f);
            while ((m + 1) * (m + 2) / 2 <= p) m++;
            while (m * (m + 1) / 2 > p) m--;
            int off = p - m * (m + 1) / 2;
            int j  = 39 - m;      // k+1 .. 39
            int i2 = 39 - off;    // j .. 39
            float2 a  = sM[i2 * 48 + k];
            float2 b2 = sM[j * 48 + k];
            float cre = a.x * b2.x + a.y * b2.y;   // a * conj(b)
            float cim = a.y * b2.x - a.x * b2.y;
            float2 v = sM[i2 * 48 + j];
            v.x -= cre; v.y -= cim;
            sM[i2 * 48 + j] = v;
        }
        __syncthreads();
    }

    // ---------------- triangular solves: 8 warps, 1 RHS each -------------
    {
        int warp = tid >> 5, lane = tid & 31;
        int col = 40 + warp;
        // forward: L y = b
        for (int i = 0; i < Dn; i++) {
            float sre = 0.f, sim = 0.f;
            for (int j = lane; j < i; j += 32) {
                float2 l = sM[i * 48 + j];
                float2 y = sM[j * 48 + col];
                sre += l.x * y.x - l.y * y.y;
                sim += l.x * y.y + l.y * y.x;
            }
            #pragma unroll
            for (int o = 16; o; o >>= 1) {
                sre += __shfl_down_sync(0xffffffffu, sre, o);
                sim += __shfl_down_sync(0xffffffffu, sim, o);
            }
            if (lane == 0) {
                float2 b = sM[i * 48 + col];
                float inv = 1.0f / sM[i * 48 + i].x;
                sM[i * 48 + col] = make_float2((b.x - sre) * inv, (b.y - sim) * inv);
            }
            __syncwarp();
        }
        // backward: L^H x = y
        for (int i = Dn - 1; i >= 0; i--) {
            float sre = 0.f, sim = 0.f;
            for (int j = i + 1 + lane; j < Dn; j += 32) {
                float2 l = sM[j * 48 + i];
                float2 x = sM[j * 48 + col];
                sre += l.x * x.x + l.y * x.y;       // conj(l) * x
                sim += l.x * x.y - l.y * x.x;
            }
            #pragma unroll
            for (int o = 16; o; o >>= 1) {
                sre += __shfl_down_sync(0xffffffffu, sre, o);
                sim += __shfl_down_sync(0xffffffffu, sim, o);
            }
            if (lane == 0) {
                float2 y = sM[i * 48 + col];
                float inv = 1.0f / sM[i * 48 + i].x;
                sM[i * 48 + col] = make_float2((y.x - sre) * inv, (y.y - sim) * inv);
            }
            __syncwarp();
        }
    }
    __syncthreads();

    // ---------------- Phase 3: rebuild Y channel-major in smem ------------
    float2 tmp[16];
    #pragma unroll
    for (int q = 0; q < 16; q++) tmp[q] = sY[tid + q * 256];
    __syncthreads();
    #pragma unroll
    for (int q = 0; q < 16; q++) {
        int idx = tid + q * 256;
        int t = idx >> 3, c = idx & 7;
        sYt[c * 517 + t] = tmp[q];
    }
    __syncthreads();

    // ---------------- tail subtraction + write -----------------------------
    float2* gEp = g_E + (size_t)bf * (Cn * Tn);
    #pragma unroll
    for (int p = 0; p < 2; p++) {
        int t = tid + p * 256;
        float oR[8], oI[8];
        #pragma unroll
        for (int e = 0; e < 8; e++) {
            float2 v = sYt[e * 517 + t];
            oR[e] = v.x; oI[e] = v.y;
        }
        #pragma unroll
        for (int tau = 0; tau < 5; tau++) {
            int ts = t - (3 + tau);
            bool ok = (ts >= 0);
            #pragma unroll
            for (int d = 0; d < 8; d++) {
                float2 y = ok ? sYt[d * 517 + ts] : make_float2(0.f, 0.f);
                int i = tau * 8 + d;
                #pragma unroll
                for (int e = 0; e < 8; e++) {
                    float2 g = sM[i * 48 + 40 + e];
                    oR[e] -= g.x * y.x - g.y * y.y;
                    oI[e] -= g.x * y.y + g.y * y.x;
                }
            }
        }
        #pragma unroll
        for (int e = 0; e < 8; e++)
            gEp[e * Tn + t] = make_float2(oR[e], oI[e]);
    }
}

// ---------------------------------------------------------------------------
// Kernel 3: (b,f,c,t) -> (B,T,C,F) re/im with ilens mask
// ---------------------------------------------------------------------------
__global__ __launch_bounds__(256) void k_out(float* __restrict__ outRe,
                                             float* __restrict__ outIm,
                                             const int* __restrict__ ilens) {
    __shared__ float2 tile[32][33];
    int b  = blockIdx.z;
    int t0 = blockIdx.y * 32;
    int f0 = blockIdx.x * 32;
    int len = ilens[b];
    int tid = threadIdx.x;
    int l32 = tid & 31, q = tid >> 5;

    for (int c = 0; c < 8; c++) {
        __syncthreads();
        for (int fr = q; fr < 32; fr += 8) {
            int f = f0 + fr;
            int t = t0 + l32;
            if (f < Fn)
                tile[fr][l32] = g_E[((size_t)(b * Fn + f) * 8 + c) * Tn + t];
        }
        __syncthreads();
        for (int tr = q; tr < 32; tr += 8) {
            int t = t0 + tr;
            int f = f0 + l32;
            if (f < Fn) {
                float2 v = tile[l32][tr];
                if (t >= len) { v.x = 0.f; v.y = 0.f; }
                size_t o = ((size_t)(b * Tn + t) * 8 + c) * Fn + f;
                outRe[o] = v.x;
                outIm[o] = v.y;
            }
        }
    }
}

// ---------------------------------------------------------------------------
extern "C" void kernel_launch(void* const* d_in, const int* in_sizes, int n_in,
                              void* d_out, int out_size) {
    const float* re = (const float*)d_in[0];
    const float* im = (const float*)d_in[1];
    const int* ilens = (const int*)d_in[2];
    float* outRe = (float*)d_out;
    float* outIm = outRe + (size_t)NBTCF;
    float* outP  = outRe + (size_t)2 * NBTCF;

    k_prep<<<dim3(Tn / 8, Bn), 256>>>(re, im, outP);
    k_wpe<<<BFn, 256>>>();
    k_out<<<dim3((Fn + 31) / 32, Tn / 32, Bn), 256>>>(outRe, outIm, ilens);
}

// round 2
// speedup vs baseline: 2.7604x; 2.7604x over previous
#include <cuda_runtime.h>

#define Bn 4
#define Tn 512
#define Cn 8
#define Fn 257
#define BFn (Bn*Fn)            // 1028
#define Dn 40
#define TPn 505                // T - delay - taps + 1
#define NBTCF (Bn*Tn*Cn*Fn)    // 4210688

typedef unsigned long long u64;

// Workspaces (no allocation allowed)
__device__ float2 g_Y[(size_t)BFn * Tn * Cn];   // (b,f,t,c) interleaved complex
__device__ float  g_w[(size_t)BFn * Tn];        // inverse power weights
__device__ float2 g_E[(size_t)BFn * Cn * Tn];   // enhanced, (b,f,c,t)

// ---- packed f32x2 helpers -------------------------------------------------
__device__ __forceinline__ u64 pk(float lo, float hi) {
    u64 r; asm("mov.b64 %0,{%1,%2};" : "=l"(r) : "f"(lo), "f"(hi)); return r;
}
__device__ __forceinline__ u64 rep(float x) { return pk(x, x); }
__device__ __forceinline__ void upk(u64 v, float& lo, float& hi) {
    asm("mov.b64 {%0,%1},%2;" : "=f"(lo), "=f"(hi) : "l"(v));
}
__device__ __forceinline__ u64 f2fma(u64 a, u64 b, u64 c) {
    u64 d; asm("fma.rn.f32x2 %0,%1,%2,%3;" : "=l"(d) : "l"(a), "l"(b), "l"(c)); return d;
}
__device__ __forceinline__ u64 f2mul(u64 a, u64 b) {
    u64 d; asm("mul.rn.f32x2 %0,%1,%2;" : "=l"(d) : "l"(a), "l"(b)); return d;
}

// ---------------------------------------------------------------------------
// Kernel 1: pack (B,T,C,F) re/im -> (b,f,t,c) float2 (coalesced via smem),
//           compute power + 1/power
// ---------------------------------------------------------------------------
__global__ __launch_bounds__(256) void k_prep(const float* __restrict__ re,
                                              const float* __restrict__ im,
                                              float* __restrict__ outP) {
    __shared__ float2 tile[32][66];
    __shared__ float  sP[32][9];
    int b  = blockIdx.z;
    int f0 = blockIdx.y * 32;
    int t0 = blockIdx.x * 8;
    int tid = threadIdx.x;
    int fl = tid & 31, g = tid >> 5;
    int f = f0 + fl;
    float acc = 0.f;
    if (f < Fn) {
        const float* pr = re + ((size_t)((b * Tn + t0 + g) * Cn)) * Fn + f;
        const float* pi = im + ((size_t)((b * Tn + t0 + g) * Cn)) * Fn + f;
        #pragma unroll
        for (int c = 0; c < 8; c++) {
            float rr = pr[c * Fn], ii = pi[c * Fn];
            tile[fl][g * 8 + c] = make_float2(rr, ii);
            acc += rr * rr + ii * ii;
        }
    }
    sP[fl][g] = fmaxf(acc * 0.125f, 1e-6f);
    __syncthreads();

    int fl3 = tid >> 3, tl3 = tid & 7;
    int f3 = f0 + fl3;
    if (f3 < Fn) {
        float pv = sP[fl3][tl3];
        int pidx = (b * Fn + f3) * Tn + t0 + tl3;
        outP[pidx] = pv;
        g_w[pidx]  = 1.0f / pv;
        // g_Y: (b,f,t,c); thread writes 8 consecutive float2 (64B)
        float2* dst = g_Y + ((size_t)(b * Fn + f3) * Tn + t0) * Cn + tl3 * 8;
        const float2* src = &tile[fl3][tl3 * 8];
        #pragma unroll
        for (int q = 0; q < 4; q++)
            *(float4*)(dst + q * 2) = *(const float4*)(src + q * 2);
    }
}

// ---------------------------------------------------------------------------
// Kernel 2: per-(b,f) WPE. 1028 blocks, 256 threads.
// ---------------------------------------------------------------------------
__global__ __launch_bounds__(256) void k_wpe() {
    const int bf  = blockIdx.x;
    const int tid = threadIdx.x;

    // shared layout (regions reused across phases):
    //  [0,16384)       sYre plane [t*8+c]        (phase 1)
    //  [16384,32768)   sYim plane                (phase 1)
    //  [32768,34816)   sw (aliases sM head; sw dead before deposit)
    //  [32768,48128)   sM 40x48 complex          (deposit/GJ load)
    //  [43008,48128)   gpA/gpB packed G          (after GJ; sM dead)
    //  [0,33088)       sYt c-major [c*517+t]     (tail; planes dead)
    //  [48128,48836)   GJ buffers + eps
    __shared__ __align__(16) char s_raw[48836];
    float*  sYre = (float*)s_raw;
    float*  sYim = (float*)(s_raw + 16384);
    float*  sw   = (float*)(s_raw + 32768);
    float2* sM   = (float2*)(s_raw + 32768);
    u64*    gpA  = (u64*)(s_raw + 43008);
    u64*    gpB  = (u64*)(s_raw + 45568);
    u64*    scol = (u64*)(s_raw + 48128);
    u64*    prow = (u64*)(s_raw + 48448);
    float*  sEps = (float*)(s_raw + 48832);
    float2* sYt  = (float2*)s_raw;

    // ---------------- load planes + weights --------------------------------
    {
        const float2* Yg = g_Y + (size_t)bf * (Tn * Cn);
        #pragma unroll
        for (int q = 0; q < 16; q++) {
            int idx = tid + q * 256;
            float2 v = Yg[idx];
            sYre[idx] = v.x; sYim[idx] = v.y;
        }
        for (int idx = tid; idx < Tn; idx += 256)
            sw[idx] = g_w[(size_t)bf * Tn + idx];
    }
    __syncthreads();

    // ---------------- Phase 1: M = [R | P] accumulation (upper tiles) ------
    int tile = tid % 75;
    int ph   = tid / 75;      // 0,1,2 active; 3 idle
    int it = 0, r2 = tile;
    while (r2 >= 12 - it) { r2 -= 12 - it; it++; }
    int jt = it + r2;
    int aOff = (4 - (it >> 1)) * 8 + (it & 1) * 4;
    int bOff = (jt >= 10) ? (7 * 8 + (jt - 10) * 4)
                          : ((4 - (jt >> 1)) * 8 + (jt & 1) * 4);

    u64 accR[2][4], accI[2][4];
    #pragma unroll
    for (int rp = 0; rp < 2; rp++)
        #pragma unroll
        for (int s = 0; s < 4; s++) { accR[rp][s] = 0ull; accI[rp][s] = 0ull; }

    if (ph < 3) {
        for (int t = ph; t < TPn; t += 3) {
            float w = sw[t + 7];
            u64 wp = rep(w), wn = rep(-w);
            const float* ar = sYre + t * 8 + aOff;
            const float* ai = sYim + t * 8 + aOff;
            u64 ax0 = *(const u64*)ar, ax1 = *(const u64*)(ar + 2);
            u64 ay0 = *(const u64*)ai, ay1 = *(const u64*)(ai + 2);
            u64 axw0  = f2mul(ax0, wp), axw1  = f2mul(ax1, wp);
            u64 ayw0  = f2mul(ay0, wp), ayw1  = f2mul(ay1, wp);
            u64 aywn0 = f2mul(ay0, wn), aywn1 = f2mul(ay1, wn);
            float4 bxv = *(const float4*)(sYre + t * 8 + bOff);
            float4 byv = *(const float4*)(sYim + t * 8 + bOff);
            float bx[4] = {bxv.x, bxv.y, bxv.z, bxv.w};
            float by[4] = {byv.x, byv.y, byv.z, byv.w};
            #pragma unroll
            for (int s = 0; s < 4; s++) {
                u64 Bx = rep(bx[s]), By = rep(by[s]);
                accR[0][s] = f2fma(axw0, Bx, f2fma(ayw0,  By, accR[0][s]));
                accR[1][s] = f2fma(axw1, Bx, f2fma(ayw1,  By, accR[1][s]));
                accI[0][s] = f2fma(axw0, By, f2fma(aywn0, Bx, accI[0][s]));
                accI[1][s] = f2fma(axw1, By, f2fma(aywn1, Bx, accI[1][s]));
            }
        }
    }
    __syncthreads();   // all reads of planes/sw done before sM deposit

    float fR[4][4], fI[4][4];
    #pragma unroll
    for (int rp = 0; rp < 2; rp++)
        #pragma unroll
        for (int s = 0; s < 4; s++) {
            upk(accR[rp][s], fR[2 * rp][s], fR[2 * rp + 1][s]);
            upk(accI[rp][s], fI[2 * rp][s], fI[2 * rp + 1][s]);
        }

    if (ph == 1) {
        #pragma unroll
        for (int r = 0; r < 4; r++)
            #pragma unroll
            for (int s = 0; s < 4; s++)
                sM[(it * 4 + r) * 48 + jt * 4 + s] = make_float2(fR[r][s], fI[r][s]);
    }
    __syncthreads();
    if (ph == 2) {
        #pragma unroll
        for (int r = 0; r < 4; r++)
            #pragma unroll
            for (int s = 0; s < 4; s++) {
                int idx = (it * 4 + r) * 48 + jt * 4 + s;
                float2 v = sM[idx];
                v.x += fR[r][s]; v.y += fI[r][s];
                sM[idx] = v;
            }
    }
    __syncthreads();
    if (ph == 0) {
        #pragma unroll
        for (int r = 0; r < 4; r++)
            #pragma unroll
            for (int s = 0; s < 4; s++) {
                int i = it * 4 + r, j = jt * 4 + s;
                float2 v = sM[i * 48 + j];
                v.x += fR[r][s]; v.y += fI[r][s];
                sM[i * 48 + j] = v;
                if (jt < 10 && jt > it)
                    sM[j * 48 + i] = make_float2(v.x, -v.y);
            }
    }
    __syncthreads();

    // ---------------- diag loading -----------------------------------------
    if (tid == 0) {
        float tr = 0.f;
        for (int i = 0; i < Dn; i++) tr += sM[i * 48 + i].x;
        *sEps = 1e-10f * tr / (float)Dn;
    }
    __syncthreads();
    if (tid < Dn) sM[tid * 48 + tid].x += *sEps;
    __syncthreads();

    // ---------------- Gauss-Jordan on [R | P], rows in registers -----------
    const bool act = tid < 240;
    const int  gi  = tid / 6;            // row 0..39
    const int  j0  = (tid % 6) * 8;      // chunk start col
    u64 row[8];
    if (act) {
        #pragma unroll
        for (int j = 0; j < 8; j++)
            row[j] = *(const u64*)&sM[gi * 48 + j0 + j];
    }
    __syncthreads();

    for (int k = 0; k < Dn; k++) {
        if (act && (unsigned)(k - j0) < 8u) scol[gi] = row[k - j0];
        __syncthreads();
        float akr, aki; upk(scol[k], akr, aki);
        float inv = 1.0f / akr;
        if (act && gi == k) {
            u64 ip = rep(inv);
            #pragma unroll
            for (int j = 0; j < 8; j++) {
                row[j] = f2mul(row[j], ip);
                prow[j0 + j] = row[j];
            }
        }
        __syncthreads();
        if (act && gi != k) {
            float fr, fi2; upk(scol[gi], fr, fi2);
            u64 fA = pk(-fr, -fr), fB = pk(fi2, -fi2);
            #pragma unroll
            for (int j = 0; j < 8; j++) {
                u64 pA = prow[j0 + j];
                float pr_, pi_; upk(pA, pr_, pi_);
                u64 pB = pk(pi_, pr_);
                row[j] = f2fma(fA, pA, f2fma(fB, pB, row[j]));
            }
        }
        __syncthreads();
    }

    // ---------------- pack G for tail, rebuild Y c-major -------------------
    if (act && j0 == 40) {
        #pragma unroll
        for (int e = 0; e < 8; e++) {
            float gr, gi2; upk(row[e], gr, gi2);
            gpA[gi * 8 + e] = pk(-gr, -gr);
            gpB[gi * 8 + e] = pk(gi2, -gi2);
        }
    }
    float tR[16], tI[16];
    #pragma unroll
    for (int q = 0; q < 16; q++) {
        int idx = tid + q * 256;
        tR[q] = sYre[idx]; tI[q] = sYim[idx];
    }
    __syncthreads();
    #pragma unroll
    for (int q = 0; q < 16; q++) {
        int idx = tid + q * 256;
        sYt[(idx & 7) * 517 + (idx >> 3)] = make_float2(tR[q], tI[q]);
    }
    __syncthreads();

    // ---------------- tail subtraction + write -----------------------------
    float2* gEp = g_E + (size_t)bf * (Cn * Tn);
    #pragma unroll
    for (int p = 0; p < 2; p++) {
        int t = tid + p * 256;
        u64 o[8];
        #pragma unroll
        for (int e = 0; e < 8; e++)
            o[e] = *(const u64*)&sYt[e * 517 + t];
        #pragma unroll 1
        for (int i = 0; i < 40; i++) {
            int tau = i >> 3, d = i & 7;
            int ts = t - 3 - tau;
            if (ts >= 0) {
                u64 yA = *(const u64*)&sYt[d * 517 + ts];
                float yr, yi; upk(yA, yr, yi);
                u64 yB = pk(yi, yr);
                #pragma unroll
                for (int e = 0; e < 8; e++)
                    o[e] = f2fma(gpA[i * 8 + e], yA, f2fma(gpB[i * 8 + e], yB, o[e]));
            }
        }
        #pragma unroll
        for (int e = 0; e < 8; e++) {
            float a, b2; upk(o[e], a, b2);
            gEp[e * Tn + t] = make_float2(a, b2);
        }
    }
}

// ---------------------------------------------------------------------------
// Kernel 3: (b,f,c,t) -> (B,T,C,F) re/im with ilens mask
// ---------------------------------------------------------------------------
__global__ __launch_bounds__(256) void k_out(float* __restrict__ outRe,
                                             float* __restrict__ outIm,
                                             const int* __restrict__ ilens) {
    __shared__ float2 tile[32][33];
    int b  = blockIdx.z;
    int t0 = blockIdx.y * 32;
    int f0 = blockIdx.x * 32;
    int len = ilens[b];
    int tid = threadIdx.x;
    int l32 = tid & 31, q = tid >> 5;

    for (int c = 0; c < 8; c++) {
        __syncthreads();
        for (int fr = q; fr < 32; fr += 8) {
            int f = f0 + fr;
            int t = t0 + l32;
            if (f < Fn)
                tile[fr][l32] = g_E[((size_t)(b * Fn + f) * 8 + c) * Tn + t];
        }
        __syncthreads();
        for (int tr = q; tr < 32; tr += 8) {
            int t = t0 + tr;
            int f = f0 + l32;
            if (f < Fn) {
                float2 v = tile[l32][tr];
                if (t >= len) { v.x = 0.f; v.y = 0.f; }
                size_t o = ((size_t)(b * Tn + t) * 8 + c) * Fn + f;
                outRe[o] = v.x;
                outIm[o] = v.y;
            }
        }
    }
}

// ---------------------------------------------------------------------------
extern "C" void kernel_launch(void* const* d_in, const int* in_sizes, int n_in,
                              void* d_out, int out_size) {
    const float* re = (const float*)d_in[0];
    const float* im = (const float*)d_in[1];
    const int* ilens = (const int*)d_in[2];
    float* outRe = (float*)d_out;
    float* outIm = outRe + (size_t)NBTCF;
    float* outP  = outRe + (size_t)2 * NBTCF;

    k_prep<<<dim3(Tn / 8, 9, Bn), 256>>>(re, im, outP);
    k_wpe<<<BFn, 256>>>();
    k_out<<<dim3((Fn + 31) / 32, Tn / 32, Bn), 256>>>(outRe, outIm, ilens);
}

// round 3
// speedup vs baseline: 2.7971x; 1.0133x over previous
#include <cuda_runtime.h>

#define Bn 4
#define Tn 512
#define Cn 8
#define Fn 257
#define BFn (Bn*Fn)            // 1028
#define Dn 40
#define TPn 505                // T - delay - taps + 1
#define NBTCF (Bn*Tn*Cn*Fn)    // 4210688

typedef unsigned long long u64;

// Workspaces (no allocation allowed)
__device__ float2 g_Y[(size_t)BFn * Tn * Cn];   // (b,f,t,c) interleaved complex
__device__ float  g_w[(size_t)BFn * Tn];        // inverse power weights
__device__ float2 g_E[(size_t)BFn * Cn * Tn];   // enhanced, (b,f,c,t)

// ---- packed f32x2 helpers -------------------------------------------------
__device__ __forceinline__ u64 pk(float lo, float hi) {
    u64 r; asm("mov.b64 %0,{%1,%2};" : "=l"(r) : "f"(lo), "f"(hi)); return r;
}
__device__ __forceinline__ u64 rep(float x) { return pk(x, x); }
__device__ __forceinline__ void upk(u64 v, float& lo, float& hi) {
    asm("mov.b64 {%0,%1},%2;" : "=f"(lo), "=f"(hi) : "l"(v));
}
__device__ __forceinline__ u64 f2fma(u64 a, u64 b, u64 c) {
    u64 d; asm("fma.rn.f32x2 %0,%1,%2,%3;" : "=l"(d) : "l"(a), "l"(b), "l"(c)); return d;
}
__device__ __forceinline__ u64 f2mul(u64 a, u64 b) {
    u64 d; asm("mul.rn.f32x2 %0,%1,%2;" : "=l"(d) : "l"(a), "l"(b)); return d;
}

// ---------------------------------------------------------------------------
// Kernel 1: pack (B,T,C,F) re/im -> (b,f,t,c) float2 (coalesced via smem),
//           compute power + 1/power. Separate re/im planes, odd width ->
//           conflict-free writes, <=2-way reads.
// ---------------------------------------------------------------------------
__global__ __launch_bounds__(256) void k_prep(const float* __restrict__ re,
                                              const float* __restrict__ im,
                                              float* __restrict__ outP) {
    __shared__ float sRe[32][65];
    __shared__ float sIm[32][65];
    __shared__ float sP[32][9];
    int b  = blockIdx.z;
    int f0 = blockIdx.y * 32;
    int t0 = blockIdx.x * 8;
    int tid = threadIdx.x;
    int fl = tid & 31, g = tid >> 5;
    int f = f0 + fl;
    float acc = 0.f;
    if (f < Fn) {
        const float* pr = re + ((size_t)((b * Tn + t0 + g) * Cn)) * Fn + f;
        const float* pi = im + ((size_t)((b * Tn + t0 + g) * Cn)) * Fn + f;
        #pragma unroll
        for (int c = 0; c < 8; c++) {
            float rr = pr[c * Fn], ii = pi[c * Fn];
            sRe[fl][g * 8 + c] = rr;
            sIm[fl][g * 8 + c] = ii;
            acc += rr * rr + ii * ii;
        }
    }
    sP[fl][g] = fmaxf(acc * 0.125f, 1e-6f);
    __syncthreads();

    int fl3 = tid >> 3, tl3 = tid & 7;
    int f3 = f0 + fl3;
    if (f3 < Fn) {
        float pv = sP[fl3][tl3];
        int pidx = (b * Fn + f3) * Tn + t0 + tl3;
        outP[pidx] = pv;
        g_w[pidx]  = 1.0f / pv;
        float rr[8], ii[8];
        #pragma unroll
        for (int c = 0; c < 8; c++) {
            rr[c] = sRe[fl3][tl3 * 8 + c];
            ii[c] = sIm[fl3][tl3 * 8 + c];
        }
        float2* dst = g_Y + ((size_t)(b * Fn + f3) * Tn + t0) * Cn + tl3 * 8;
        #pragma unroll
        for (int q = 0; q < 4; q++)
            *(float4*)(dst + q * 2) = make_float4(rr[2*q], ii[2*q], rr[2*q+1], ii[2*q+1]);
    }
}

// ---------------------------------------------------------------------------
// Kernel 2: per-(b,f) WPE. 1028 blocks, 256 threads, 3 blocks/SM.
// ---------------------------------------------------------------------------
__global__ __launch_bounds__(256, 3) void k_wpe() {
    const int bf  = blockIdx.x;
    const int tid = threadIdx.x;

    // shared layout (regions reused across phases):
    //  [0,16384)       sYre plane [t*8+c]        (phase 1)
    //  [16384,32768)   sYim plane                (phase 1)
    //  [32768,34816)   sw (aliases sM head; sw dead before deposit)
    //  [32768,48128)   sM 40x48 complex          (deposit/GJ load)
    //  [43008,48128)   gpAB packed G float4      (after GJ; sM dead)
    //  [0,33088)       sYt c-major [c*517+t]     (tail; planes dead)
    //  [48128,48836)   GJ buffers + eps
    __shared__ __align__(16) char s_raw[48836];
    float*  sYre = (float*)s_raw;
    float*  sYim = (float*)(s_raw + 16384);
    float*  sw   = (float*)(s_raw + 32768);
    float2* sM   = (float2*)(s_raw + 32768);
    float4* gpAB = (float4*)(s_raw + 43008);
    u64*    scol = (u64*)(s_raw + 48128);
    u64*    prow = (u64*)(s_raw + 48448);
    float*  sEps = (float*)(s_raw + 48832);
    float2* sYt  = (float2*)s_raw;

    // ---------------- load planes + weights --------------------------------
    {
        const float2* Yg = g_Y + (size_t)bf * (Tn * Cn);
        #pragma unroll
        for (int q = 0; q < 16; q++) {
            int idx = tid + q * 256;
            float2 v = Yg[idx];
            sYre[idx] = v.x; sYim[idx] = v.y;
        }
        for (int idx = tid; idx < Tn; idx += 256)
            sw[idx] = g_w[(size_t)bf * Tn + idx];
    }
    __syncthreads();

    // ---------------- Phase 1: M = [R | P] accumulation (upper tiles) ------
    int tile = tid % 75;
    int ph   = tid / 75;      // 0,1,2 active; 3 idle
    int it = 0, r2 = tile;
    while (r2 >= 12 - it) { r2 -= 12 - it; it++; }
    int jt = it + r2;
    int aOff = (4 - (it >> 1)) * 8 + (it & 1) * 4;
    int bOff = (jt >= 10) ? (7 * 8 + (jt - 10) * 4)
                          : ((4 - (jt >> 1)) * 8 + (jt & 1) * 4);

    u64 accR[2][4], accI[2][4];
    #pragma unroll
    for (int rp = 0; rp < 2; rp++)
        #pragma unroll
        for (int s = 0; s < 4; s++) { accR[rp][s] = 0ull; accI[rp][s] = 0ull; }

    if (ph < 3) {
        for (int t = ph; t < TPn; t += 3) {
            float w = sw[t + 7];
            u64 wp = rep(w), wn = rep(-w);
            const float* ar = sYre + t * 8 + aOff;
            const float* ai = sYim + t * 8 + aOff;
            u64 ax0 = *(const u64*)ar, ax1 = *(const u64*)(ar + 2);
            u64 ay0 = *(const u64*)ai, ay1 = *(const u64*)(ai + 2);
            u64 axw0  = f2mul(ax0, wp), axw1  = f2mul(ax1, wp);
            u64 ayw0  = f2mul(ay0, wp), ayw1  = f2mul(ay1, wp);
            u64 aywn0 = f2mul(ay0, wn), aywn1 = f2mul(ay1, wn);
            float4 bxv = *(const float4*)(sYre + t * 8 + bOff);
            float4 byv = *(const float4*)(sYim + t * 8 + bOff);
            float bx[4] = {bxv.x, bxv.y, bxv.z, bxv.w};
            float by[4] = {byv.x, byv.y, byv.z, byv.w};
            #pragma unroll
            for (int s = 0; s < 4; s++) {
                u64 Bx = rep(bx[s]), By = rep(by[s]);
                accR[0][s] = f2fma(axw0, Bx, f2fma(ayw0,  By, accR[0][s]));
                accR[1][s] = f2fma(axw1, Bx, f2fma(ayw1,  By, accR[1][s]));
                accI[0][s] = f2fma(axw0, By, f2fma(aywn0, Bx, accI[0][s]));
                accI[1][s] = f2fma(axw1, By, f2fma(aywn1, Bx, accI[1][s]));
            }
        }
    }
    __syncthreads();   // all reads of planes/sw done before sM deposit

    float fR[4][4], fI[4][4];
    #pragma unroll
    for (int rp = 0; rp < 2; rp++)
        #pragma unroll
        for (int s = 0; s < 4; s++) {
            upk(accR[rp][s], fR[2 * rp][s], fR[2 * rp + 1][s]);
            upk(accI[rp][s], fI[2 * rp][s], fI[2 * rp + 1][s]);
        }

    if (ph == 1) {
        #pragma unroll
        for (int r = 0; r < 4; r++)
            #pragma unroll
            for (int s = 0; s < 4; s++)
                sM[(it * 4 + r) * 48 + jt * 4 + s] = make_float2(fR[r][s], fI[r][s]);
    }
    __syncthreads();
    if (ph == 2) {
        #pragma unroll
        for (int r = 0; r < 4; r++)
            #pragma unroll
            for (int s = 0; s < 4; s++) {
                int idx = (it * 4 + r) * 48 + jt * 4 + s;
                float2 v = sM[idx];
                v.x += fR[r][s]; v.y += fI[r][s];
                sM[idx] = v;
            }
    }
    __syncthreads();
    if (ph == 0) {
        #pragma unroll
        for (int r = 0; r < 4; r++)
            #pragma unroll
            for (int s = 0; s < 4; s++) {
                int i = it * 4 + r, j = jt * 4 + s;
                float2 v = sM[i * 48 + j];
                v.x += fR[r][s]; v.y += fI[r][s];
                sM[i * 48 + j] = v;
                if (jt < 10 && jt > it)
                    sM[j * 48 + i] = make_float2(v.x, -v.y);
            }
    }
    __syncthreads();

    // ---------------- diag loading -----------------------------------------
    if (tid == 0) {
        float tr = 0.f;
        for (int i = 0; i < Dn; i++) tr += sM[i * 48 + i].x;
        *sEps = 1e-10f * tr / (float)Dn;
    }
    __syncthreads();
    if (tid < Dn) sM[tid * 48 + tid].x += *sEps;
    __syncthreads();

    // ---------------- Gauss-Jordan on [R | P], rows in registers -----------
    const bool act = tid < 240;
    const int  gi  = tid / 6;            // row 0..39
    const int  j0  = (tid % 6) * 8;      // chunk start col
    u64 row[8];
    if (act) {
        #pragma unroll
        for (int j = 0; j < 8; j++)
            row[j] = *(const u64*)&sM[gi * 48 + j0 + j];
    }
    __syncthreads();

    for (int k = 0; k < Dn; k++) {
        if (act && (unsigned)(k - j0) < 8u) scol[gi] = row[k - j0];
        __syncthreads();
        float akr, aki; upk(scol[k], akr, aki);
        (void)aki;
        float inv = 1.0f / akr;
        if (act && gi == k) {
            u64 ip = rep(inv);
            #pragma unroll
            for (int j = 0; j < 8; j++) {
                row[j] = f2mul(row[j], ip);
                prow[j0 + j] = row[j];
            }
        }
        __syncthreads();
        if (act && gi != k) {
            float fr, fi2; upk(scol[gi], fr, fi2);
            u64 fA = pk(-fr, -fr), fB = pk(fi2, -fi2);
            #pragma unroll
            for (int j = 0; j < 8; j++) {
                u64 pA = prow[j0 + j];
                float pr_, pi_; upk(pA, pr_, pi_);
                u64 pB = pk(pi_, pr_);
                row[j] = f2fma(fA, pA, f2fma(fB, pB, row[j]));
            }
        }
        __syncthreads();
    }

    // ---------------- pack G for tail, rebuild Y c-major -------------------
    if (act && j0 == 40) {
        #pragma unroll
        for (int e = 0; e < 8; e++) {
            float gr, gi2; upk(row[e], gr, gi2);
            gpAB[gi * 8 + e] = make_float4(-gr, -gr, gi2, -gi2);
        }
    }
    float tR[16], tI[16];
    #pragma unroll
    for (int q = 0; q < 16; q++) {
        int idx = tid + q * 256;
        tR[q] = sYre[idx]; tI[q] = sYim[idx];
    }
    __syncthreads();
    #pragma unroll
    for (int q = 0; q < 16; q++) {
        int idx = tid + q * 256;
        sYt[(idx & 7) * 517 + (idx >> 3)] = make_float2(tR[q], tI[q]);
    }
    __syncthreads();

    // ---------------- tail subtraction + write -----------------------------
    float2* gEp = g_E + (size_t)bf * (Cn * Tn);
    #pragma unroll
    for (int p = 0; p < 2; p++) {
        int t = tid + p * 256;
        u64 o[8];
        #pragma unroll
        for (int e = 0; e < 8; e++)
            o[e] = *(const u64*)&sYt[e * 517 + t];
        #pragma unroll 1
        for (int i = 0; i < 40; i++) {
            int tau = i >> 3, d = i & 7;
            int ts = t - 3 - tau;
            if (ts >= 0) {
                u64 yA = *(const u64*)&sYt[d * 517 + ts];
                float yr, yi; upk(yA, yr, yi);
                u64 yB = pk(yi, yr);
                #pragma unroll
                for (int e = 0; e < 8; e++) {
                    float4 gv = gpAB[i * 8 + e];
                    u64 gA = pk(gv.x, gv.y);
                    u64 gB = pk(gv.z, gv.w);
                    o[e] = f2fma(gA, yA, f2fma(gB, yB, o[e]));
                }
            }
        }
        #pragma unroll
        for (int e = 0; e < 8; e++) {
            float a, b2; upk(o[e], a, b2);
            gEp[e * Tn + t] = make_float2(a, b2);
        }
    }
}

// ---------------------------------------------------------------------------
// Kernel 3: (b,f,c,t) -> (B,T,C,F) re/im with ilens mask.
// Separate re/im planes width 33 -> conflict-free both directions.
// ---------------------------------------------------------------------------
__global__ __launch_bounds__(256) void k_out(float* __restrict__ outRe,
                                             float* __restrict__ outIm,
                                             const int* __restrict__ ilens) {
    __shared__ float tRe[32][33];
    __shared__ float tIm[32][33];
    int b  = blockIdx.z;
    int t0 = blockIdx.y * 32;
    int f0 = blockIdx.x * 32;
    int len = ilens[b];
    int tid = threadIdx.x;
    int l32 = tid & 31, q = tid >> 5;

    for (int c = 0; c < 8; c++) {
        __syncthreads();
        for (int fr = q; fr < 32; fr += 8) {
            int f = f0 + fr;
            int t = t0 + l32;
            if (f < Fn) {
                float2 v = g_E[((size_t)(b * Fn + f) * 8 + c) * Tn + t];
                tRe[fr][l32] = v.x;
                tIm[fr][l32] = v.y;
            }
        }
        __syncthreads();
        for (int tr = q; tr < 32; tr += 8) {
            int t = t0 + tr;
            int f = f0 + l32;
            if (f < Fn) {
                float vr = tRe[l32][tr];
                float vi = tIm[l32][tr];
                if (t >= len) { vr = 0.f; vi = 0.f; }
                size_t o = ((size_t)(b * Tn + t) * 8 + c) * Fn + f;
                outRe[o] = vr;
                outIm[o] = vi;
            }
        }
    }
}

// ---------------------------------------------------------------------------
extern "C" void kernel_launch(void* const* d_in, const int* in_sizes, int n_in,
                              void* d_out, int out_size) {
    const float* re = (const float*)d_in[0];
    const float* im = (const float*)d_in[1];
    const int* ilens = (const int*)d_in[2];
    float* outRe = (float*)d_out;
    float* outIm = outRe + (size_t)NBTCF;
    float* outP  = outRe + (size_t)2 * NBTCF;

    k_prep<<<dim3(Tn / 8, 9, Bn), 256>>>(re, im, outP);
    k_wpe<<<BFn, 256>>>();
    k_out<<<dim3((Fn + 31) / 32, Tn / 32, Bn), 256>>>(outRe, outIm, ilens);
}